// round 9
// baseline (speedup 1.0000x reference)
#include <cuda_runtime.h>
#include <math.h>

#define H 512
#define B 256
#define T 512
#define DIN 64
#define KC 32           // k-chunk size
#define NCTA 128
#define NTHR 256

// ---------------- persistent device state (allocation-free) ----------------
__device__ float g_xT[(size_t)T * DIN * B];          // x transposed: [t][d][b] (32 MB)
__device__ float g_h1seqT[(size_t)T * H * B];        // layer-0 output: [t][j][b] (256 MB)
__device__ float g_hT0[2][H * B];                    // layer-0 hidden, [j][b], double-buffered
__device__ float g_hT1[2][H * B];                    // layer-1 hidden
__device__ float g_cT0[H * B];                       // cells, [j][b]
__device__ float g_cT1[H * B];
__device__ unsigned g_bar_cnt;
__device__ volatile unsigned g_bar_phase;

// ---------------- helpers ----------------
#define FMAX2(d, a, b) asm("fma.rn.f32x2 %0, %1, %2, %0;" : "+l"(d) : "l"(a), "l"(b))

__device__ __forceinline__ void cp_async16(void* s, const void* g) {
    unsigned sa = (unsigned)__cvta_generic_to_shared(s);
    asm volatile("cp.async.cg.shared.global [%0], [%1], 16;" :: "r"(sa), "l"(g));
}
#define CP_COMMIT() asm volatile("cp.async.commit_group;")
#define CP_WAIT0()  asm volatile("cp.async.wait_group 0;")
#define CP_WAIT1()  asm volatile("cp.async.wait_group 1;")

__device__ __forceinline__ float2 unpack2(unsigned long long v) {
    float2 r;
    r.x = __uint_as_float((unsigned)v);
    r.y = __uint_as_float((unsigned)(v >> 32));
    return r;
}

__device__ __forceinline__ void grid_barrier(unsigned target) {
    __threadfence();
    __syncthreads();
    if (threadIdx.x == 0) {
        unsigned a = atomicAdd(&g_bar_cnt, 1);
        if (a == gridDim.x - 1) {
            g_bar_cnt = 0;
            __threadfence();
            g_bar_phase = target;           // release
        } else {
            while (g_bar_phase < target) {} // spin
        }
        __threadfence();
    }
    __syncthreads();
}

// ---------------- single persistent kernel ----------------
// 128 CTAs x 256 threads. CTA bx owns hidden units [4*bx, 4*bx+4), all 256 batch,
// all 4 gates. Thread tile: 1 unit x 4 gates x 4 batches.
// f32x2 pairs run over adjacent BATCHES (A loads straight from SMEM as u64);
// W is pre-splatted (w,w) in SMEM -> zero pack/mov instructions in the hot loop.
__global__ __launch_bounds__(NTHR, 1) void lstm_persist(
    const float* __restrict__ x,
    const float* __restrict__ W_ih0, const float* __restrict__ W_hh0,
    const float* __restrict__ b_ih0, const float* __restrict__ b_hh0,
    const float* __restrict__ W_ih1, const float* __restrict__ W_hh1,
    const float* __restrict__ b_ih1, const float* __restrict__ b_hh1,
    const float* __restrict__ fcW,  const float* __restrict__ fcb,
    float* __restrict__ out)
{
    extern __shared__ char smem[];
    float* Abuf = (float*)smem;                // 2 x KC*B floats = 64 KB
    float* Wsh  = (float*)(smem + 65536);      // [K_tot][unit(4)][gate(4)][2] = up to 128 KB

    const int tid  = threadIdx.x;
    const int bgrp = tid & 63;        // batch group (0..63), 4 batches each
    const int ugrp = tid >> 6;        // unit (0..3) within CTA
    const int jblk = blockIdx.x * 4;  // CTA's first hidden unit
    const int jglob = jblk + ugrp;

    const unsigned base = g_bar_phase;   // base-relative barrier (graph replays)
    unsigned phase = 0;

    // ---- init hidden/cell state ----
    for (int i = blockIdx.x * NTHR + tid; i < H * B; i += NCTA * NTHR) {
        g_hT0[0][i] = 0.f; g_cT0[i] = 0.f;
        g_hT1[0][i] = 0.f; g_cT1[i] = 0.f;
    }

    // ---- transpose x: [b][t][d] -> xT[t][d][b], 32x64 tiles via smem ----
    {
        float* tile = Abuf;  // 32*65 floats, reused
        for (int ti = blockIdx.x; ti < T * (B / 32); ti += NCTA) {
            int t = ti >> 3;
            int bblk = (ti & 7) * 32;
            for (int i = tid; i < 32 * 64; i += NTHR) {
                int b = i >> 6, d = i & 63;
                tile[b * 65 + d] = x[((size_t)(bblk + b) * T + t) * DIN + d];
            }
            __syncthreads();
            for (int i = tid; i < 32 * 64; i += NTHR) {
                int d = i >> 5, b = i & 31;
                g_xT[((size_t)t * DIN + d) * B + bblk + b] = tile[b * 65 + d];
            }
            __syncthreads();
        }
    }
    grid_barrier(base + ++phase);

    for (int layer = 0; layer < 2; layer++) {
        const int K1  = layer ? H : DIN;
        const int n1  = K1 / KC;
        const int nch = n1 + H / KC;
        const float* Wih = layer ? W_ih1 : W_ih0;
        const float* Whh = layer ? W_hh1 : W_hh0;
        const float* bih = layer ? b_ih1 : b_ih0;
        const float* bhh = layer ? b_hh1 : b_hh0;
        float* hbuf = layer ? g_hT1[0] : g_hT0[0];
        float* cbuf = layer ? g_cT1    : g_cT0;

        // W slice, splatted, into SMEM: Wsh[k][unit][gate][2]
        const int Ktot = K1 + H;
        for (int idx = tid; idx < Ktot * 32; idx += NTHR) {
            int k = idx >> 5, r = idx & 31;
            int u = r >> 3, g = (r >> 1) & 3;
            int row = g * H + jblk + u;
            Wsh[idx] = (k < K1) ? Wih[(size_t)row * K1 + k]
                                : Whh[(size_t)row * H + (k - K1)];
        }
        float bias[4];
        #pragma unroll
        for (int g = 0; g < 4; g++)
            bias[g] = bih[g * H + jglob] + bhh[g * H + jglob];
        __syncthreads();

        for (int t = 0; t < T; t++) {
            grid_barrier(base + ++phase);
            const float* hin  = hbuf + (t & 1) * (H * B);
            float*       hout = hbuf + ((t + 1) & 1) * (H * B);
            const float* inA  = layer ? (g_h1seqT + (size_t)t * H * B)
                                      : (g_xT     + (size_t)t * DIN * B);

            // chunk = KC*B = 8192 floats = 2048 float4 -> 8 per thread
            {
                const float* src = (0 < n1) ? inA : hin;
                #pragma unroll
                for (int i = 0; i < 8; i++) {
                    int idx = tid + i * NTHR;
                    cp_async16(Abuf + idx * 4, src + idx * 4);
                }
                CP_COMMIT();
            }

            // acc[gate][bpair]: gate order i,f,g,o; bpair 0 = batches (0,1), 1 = (2,3)
            unsigned long long acc[4][2];
            #pragma unroll
            for (int g = 0; g < 4; g++) { acc[g][0] = 0ull; acc[g][1] = 0ull; }

            for (int c = 0; c < nch; c++) {
                if (c + 1 < nch) {
                    int cn = c + 1;
                    const float* src = (cn < n1) ? (inA + (size_t)cn * KC * B)
                                                 : (hin + (size_t)(cn - n1) * KC * B);
                    float* dst = Abuf + (cn & 1) * (KC * B);
                    #pragma unroll
                    for (int i = 0; i < 8; i++) {
                        int idx = tid + i * NTHR;
                        cp_async16(dst + idx * 4, src + idx * 4);
                    }
                    CP_COMMIT();
                    CP_WAIT1();
                } else {
                    CP_WAIT0();
                }
                __syncthreads();

                const float* A  = Abuf + (c & 1) * (KC * B) + bgrp * 4;
                const float* Wk = Wsh + (size_t)c * KC * 32 + ugrp * 8;
                #pragma unroll 8
                for (int kk = 0; kk < KC; kk++) {
                    longlong2 a2  = *(const longlong2*)(A  + kk * B);   // (b0,b1),(b2,b3)
                    longlong2 wif = *(const longlong2*)(Wk + kk * 32);      // (i,i),(f,f)
                    longlong2 wgo = *(const longlong2*)(Wk + kk * 32 + 4);  // (g,g),(o,o)
                    unsigned long long a0 = (unsigned long long)a2.x;
                    unsigned long long a1 = (unsigned long long)a2.y;
                    FMAX2(acc[0][0], a0, (unsigned long long)wif.x);
                    FMAX2(acc[0][1], a1, (unsigned long long)wif.x);
                    FMAX2(acc[1][0], a0, (unsigned long long)wif.y);
                    FMAX2(acc[1][1], a1, (unsigned long long)wif.y);
                    FMAX2(acc[2][0], a0, (unsigned long long)wgo.x);
                    FMAX2(acc[2][1], a1, (unsigned long long)wgo.x);
                    FMAX2(acc[3][0], a0, (unsigned long long)wgo.y);
                    FMAX2(acc[3][1], a1, (unsigned long long)wgo.y);
                }
                __syncthreads();
            }

            // ---- fused cell update (gate order i,f,g,o) ----
            float gv[4][4];
            #pragma unroll
            for (int g = 0; g < 4; g++) {
                float2 lo = unpack2(acc[g][0]);
                float2 hi = unpack2(acc[g][1]);
                gv[g][0] = lo.x; gv[g][1] = lo.y; gv[g][2] = hi.x; gv[g][3] = hi.y;
            }
            float* cp_ = cbuf + (size_t)jglob * B + bgrp * 4;
            float4 cv = *(const float4*)cp_;
            float cold[4] = {cv.x, cv.y, cv.z, cv.w};
            float cn4[4], hn4[4];
            #pragma unroll
            for (int b = 0; b < 4; b++) {
                float gi = gv[0][b] + bias[0];
                float gf = gv[1][b] + bias[1];
                float gg = gv[2][b] + bias[2];
                float go = gv[3][b] + bias[3];
                float si = 1.f / (1.f + expf(-gi));
                float sf = 1.f / (1.f + expf(-gf));
                float so = 1.f / (1.f + expf(-go));
                float cn = sf * cold[b] + si * tanhf(gg);
                cn4[b] = cn;
                hn4[b] = so * tanhf(cn);
            }
            *(float4*)cp_ = make_float4(cn4[0], cn4[1], cn4[2], cn4[3]);
            float4 hv = make_float4(hn4[0], hn4[1], hn4[2], hn4[3]);
            *(float4*)(hout + (size_t)jglob * B + bgrp * 4) = hv;
            if (layer == 0)
                *(float4*)(g_h1seqT + ((size_t)t * H + jglob) * B + bgrp * 4) = hv;
        }
    }

    // ---------------- FC epilogue: out[b] = h2_last . fcW + fcb ----------------
    grid_barrier(base + ++phase);
    const float* hfin = g_hT1[0];   // last write t=T-1 -> buffer (T & 1) == 0
    int b0 = blockIdx.x * 2;
    float s0 = 0.f, s1 = 0.f;
    for (int j = tid; j < H; j += NTHR) {
        float w = fcW[j];
        s0 += w * hfin[(size_t)j * B + b0];
        s1 += w * hfin[(size_t)j * B + b0 + 1];
    }
    float* red = Abuf;
    red[tid] = s0; red[NTHR + tid] = s1;
    __syncthreads();
    for (int off = NTHR / 2; off > 0; off >>= 1) {
        if (tid < off) {
            red[tid] += red[tid + off];
            red[NTHR + tid] += red[NTHR + tid + off];
        }
        __syncthreads();
    }
    if (tid == 0) {
        out[b0]     = red[0]    + fcb[0];
        out[b0 + 1] = red[NTHR] + fcb[0];
    }
}

// ---------------- launch ----------------
extern "C" void kernel_launch(void* const* d_in, const int* in_sizes, int n_in,
                              void* d_out, int out_size)
{
    const float* x     = (const float*)d_in[0];
    const float* W_ih0 = (const float*)d_in[1];
    const float* W_hh0 = (const float*)d_in[2];
    const float* b_ih0 = (const float*)d_in[3];
    const float* b_hh0 = (const float*)d_in[4];
    const float* W_ih1 = (const float*)d_in[5];
    const float* W_hh1 = (const float*)d_in[6];
    const float* b_ih1 = (const float*)d_in[7];
    const float* b_hh1 = (const float*)d_in[8];
    const float* fc_W  = (const float*)d_in[9];
    const float* fc_b  = (const float*)d_in[10];
    float* out = (float*)d_out;

    cudaFuncSetAttribute(lstm_persist,
                         cudaFuncAttributeMaxDynamicSharedMemorySize, 196608);

    lstm_persist<<<NCTA, NTHR, 196608>>>(x,
                                         W_ih0, W_hh0, b_ih0, b_hh0,
                                         W_ih1, W_hh1, b_ih1, b_hh1,
                                         fc_W, fc_b, out);
}

// round 11
// speedup vs baseline: 1.2703x; 1.2703x over previous
#include <cuda_runtime.h>
#include <math.h>

#define H 512
#define B 256
#define T 512
#define DIN 64
#define KC 32           // k-chunk size
#define NCTA 128
#define NTHR 256

// ---------------- persistent device state (allocation-free) ----------------
__device__ float g_xT[(size_t)T * DIN * B];          // x transposed: [t][d][b] (32 MB)
__device__ float g_h1seqT[(size_t)T * H * B];        // layer-0 output: [t][j][b] (256 MB)
__device__ float g_hT0[2][H * B];                    // layer-0 hidden, [j][b], double-buffered
__device__ float g_hT1[2][H * B];                    // layer-1 hidden
__device__ float g_cT0[H * B];                       // cells, [j][b]
__device__ float g_cT1[H * B];
__device__ unsigned g_bar_cnt;
__device__ volatile unsigned g_bar_phase;

// ---------------- helpers ----------------
#define FMAX2(d, a, b) asm("fma.rn.f32x2 %0, %1, %2, %0;" : "+l"(d) : "l"(a), "l"(b))

__device__ __forceinline__ unsigned long long splat2(float v) {
    unsigned long long r;
    unsigned u = __float_as_uint(v);
    asm("mov.b64 %0, {%1, %1};" : "=l"(r) : "r"(u));
    return r;
}

__device__ __forceinline__ void cp_async16(void* s, const void* g) {
    unsigned sa = (unsigned)__cvta_generic_to_shared(s);
    asm volatile("cp.async.cg.shared.global [%0], [%1], 16;" :: "r"(sa), "l"(g));
}
#define CP_COMMIT() asm volatile("cp.async.commit_group;")
#define CP_WAIT0()  asm volatile("cp.async.wait_group 0;")
#define CP_WAIT1()  asm volatile("cp.async.wait_group 1;")

__device__ __forceinline__ float2 unpack2(unsigned long long v) {
    float2 r;
    r.x = __uint_as_float((unsigned)v);
    r.y = __uint_as_float((unsigned)(v >> 32));
    return r;
}

__device__ __forceinline__ void grid_barrier(unsigned target) {
    __threadfence();
    __syncthreads();
    if (threadIdx.x == 0) {
        unsigned a = atomicAdd(&g_bar_cnt, 1);
        if (a == gridDim.x - 1) {
            g_bar_cnt = 0;
            __threadfence();
            g_bar_phase = target;           // release
        } else {
            while (g_bar_phase < target) {} // spin
        }
        __threadfence();
    }
    __syncthreads();
}

// ---------------- single persistent kernel ----------------
// 128 CTAs x 256 threads (8 warps/SM). CTA bx owns hidden units [4*bx, 4*bx+4).
// Thread tile: 2 batches x 2 units x 4 gates = 8 f32x2 FMA per kk.
//   bgrp = tid & 127  -> batches (2*bgrp, 2*bgrp+1): A via one LDS.64 (2 wf/warp)
//   ugrp = tid >> 7   -> units (2*ugrp, 2*ugrp+1): warp-uniform W, 2x LDS.128 bcast
// f32x2 pairs over gates (i,f) and (g,o); A splatted with 2x mov.b64.
// Per SM-kk: crossbar 32 wf, FMA 32 cyc, issue 30/SMSP -- balanced at the floor.
__global__ __launch_bounds__(NTHR, 1) void lstm_persist(
    const float* __restrict__ x,
    const float* __restrict__ W_ih0, const float* __restrict__ W_hh0,
    const float* __restrict__ b_ih0, const float* __restrict__ b_hh0,
    const float* __restrict__ W_ih1, const float* __restrict__ W_hh1,
    const float* __restrict__ b_ih1, const float* __restrict__ b_hh1,
    const float* __restrict__ fcW,  const float* __restrict__ fcb,
    float* __restrict__ out)
{
    extern __shared__ char smem[];
    float* Abuf = (float*)smem;                // 2 x KC*B floats = 64 KB
    float* Wsh  = (float*)(smem + 65536);      // [K_tot][unit(4)][gate(4)] = up to 64 KB

    const int tid  = threadIdx.x;
    const int bgrp = tid & 127;       // batch pair index: batches 2*bgrp, 2*bgrp+1
    const int ugrp = tid >> 7;        // unit pair: units 2*ugrp, 2*ugrp+1 (warp-uniform)
    const int jblk = blockIdx.x * 4;  // CTA's first hidden unit
    const int ju0  = jblk + 2 * ugrp; // thread's first unit

    const unsigned base = g_bar_phase;   // base-relative barrier (graph replays)
    unsigned phase = 0;

    // ---- init hidden/cell state ----
    for (int i = blockIdx.x * NTHR + tid; i < H * B; i += NCTA * NTHR) {
        g_hT0[0][i] = 0.f; g_cT0[i] = 0.f;
        g_hT1[0][i] = 0.f; g_cT1[i] = 0.f;
    }

    // ---- transpose x: [b][t][d] -> xT[t][d][b], 32x64 tiles via smem ----
    {
        float* tile = Abuf;  // 32*65 floats, reused
        for (int ti = blockIdx.x; ti < T * (B / 32); ti += NCTA) {
            int t = ti >> 3;
            int bblk = (ti & 7) * 32;
            for (int i = tid; i < 32 * 64; i += NTHR) {
                int b = i >> 6, d = i & 63;
                tile[b * 65 + d] = x[((size_t)(bblk + b) * T + t) * DIN + d];
            }
            __syncthreads();
            for (int i = tid; i < 32 * 64; i += NTHR) {
                int d = i >> 5, b = i & 31;
                g_xT[((size_t)t * DIN + d) * B + bblk + b] = tile[b * 65 + d];
            }
            __syncthreads();
        }
    }
    grid_barrier(base + ++phase);

    for (int layer = 0; layer < 2; layer++) {
        const int K1  = layer ? H : DIN;
        const int n1  = K1 / KC;
        const int nch = n1 + H / KC;
        const float* Wih = layer ? W_ih1 : W_ih0;
        const float* Whh = layer ? W_hh1 : W_hh0;
        const float* bih = layer ? b_ih1 : b_ih0;
        const float* bhh = layer ? b_hh1 : b_hh0;
        float* hbuf = layer ? g_hT1[0] : g_hT0[0];
        float* cbuf = layer ? g_cT1    : g_cT0;

        // W slice into SMEM: Wsh[k][unit(4)][gate(4)] (natural, no splat)
        const int Ktot = K1 + H;
        for (int idx = tid; idx < Ktot * 16; idx += NTHR) {
            int k = idx >> 4, u = (idx >> 2) & 3, g = idx & 3;
            int row = g * H + jblk + u;
            Wsh[idx] = (k < K1) ? Wih[(size_t)row * K1 + k]
                                : Whh[(size_t)row * H + (k - K1)];
        }
        // biases: 2 units x 4 gates
        float bias[2][4];
        #pragma unroll
        for (int u = 0; u < 2; u++)
            #pragma unroll
            for (int g = 0; g < 4; g++)
                bias[u][g] = bih[g * H + ju0 + u] + bhh[g * H + ju0 + u];
        __syncthreads();

        for (int t = 0; t < T; t++) {
            grid_barrier(base + ++phase);
            const float* hin  = hbuf + (t & 1) * (H * B);
            float*       hout = hbuf + ((t + 1) & 1) * (H * B);
            const float* inA  = layer ? (g_h1seqT + (size_t)t * H * B)
                                      : (g_xT     + (size_t)t * DIN * B);

            // chunk = KC*B = 8192 floats = 2048 float4 -> 8 per thread
            {
                const float* src = (0 < n1) ? inA : hin;
                #pragma unroll
                for (int i = 0; i < 8; i++) {
                    int idx = tid + i * NTHR;
                    cp_async16(Abuf + idx * 4, src + idx * 4);
                }
                CP_COMMIT();
            }

            // acc[u][b][pair]: pair 0 = (i,f), pair 1 = (g,o)
            unsigned long long acc[2][2][2];
            #pragma unroll
            for (int u = 0; u < 2; u++)
                #pragma unroll
                for (int b = 0; b < 2; b++) { acc[u][b][0] = 0ull; acc[u][b][1] = 0ull; }

            for (int c = 0; c < nch; c++) {
                if (c + 1 < nch) {
                    int cn = c + 1;
                    const float* src = (cn < n1) ? (inA + (size_t)cn * KC * B)
                                                 : (hin + (size_t)(cn - n1) * KC * B);
                    float* dst = Abuf + (cn & 1) * (KC * B);
                    #pragma unroll
                    for (int i = 0; i < 8; i++) {
                        int idx = tid + i * NTHR;
                        cp_async16(dst + idx * 4, src + idx * 4);
                    }
                    CP_COMMIT();
                    CP_WAIT1();
                } else {
                    CP_WAIT0();
                }
                __syncthreads();

                const float* A  = Abuf + (c & 1) * (KC * B) + bgrp * 2;
                const float* Wk = Wsh + (size_t)c * KC * 16 + ugrp * 8;
                #pragma unroll 8
                for (int kk = 0; kk < KC; kk++) {
                    float2 av = *(const float2*)(A + kk * B);              // batches 2g,2g+1
                    longlong2 w0 = *(const longlong2*)(Wk + kk * 16);      // unit u0: (i,f),(g,o)
                    longlong2 w1 = *(const longlong2*)(Wk + kk * 16 + 4);  // unit u0+1
                    unsigned long long aa0 = splat2(av.x);
                    unsigned long long aa1 = splat2(av.y);
                    FMAX2(acc[0][0][0], aa0, (unsigned long long)w0.x);
                    FMAX2(acc[0][0][1], aa0, (unsigned long long)w0.y);
                    FMAX2(acc[0][1][0], aa1, (unsigned long long)w0.x);
                    FMAX2(acc[0][1][1], aa1, (unsigned long long)w0.y);
                    FMAX2(acc[1][0][0], aa0, (unsigned long long)w1.x);
                    FMAX2(acc[1][0][1], aa0, (unsigned long long)w1.y);
                    FMAX2(acc[1][1][0], aa1, (unsigned long long)w1.x);
                    FMAX2(acc[1][1][1], aa1, (unsigned long long)w1.y);
                }
                __syncthreads();
            }

            // ---- fused cell update (gate order i,f,g,o) ----
            #pragma unroll
            for (int u = 0; u < 2; u++) {
                int j = ju0 + u;
                float* cp_ = cbuf + (size_t)j * B + bgrp * 2;
                float2 cv = *(const float2*)cp_;
                float cold[2] = {cv.x, cv.y};
                float cn2[2], hn2[2];
                #pragma unroll
                for (int b = 0; b < 2; b++) {
                    float2 pif = unpack2(acc[u][b][0]);
                    float2 pgo = unpack2(acc[u][b][1]);
                    float gi = pif.x + bias[u][0];
                    float gf = pif.y + bias[u][1];
                    float gg = pgo.x + bias[u][2];
                    float go = pgo.y + bias[u][3];
                    float si = 1.f / (1.f + expf(-gi));
                    float sf = 1.f / (1.f + expf(-gf));
                    float so = 1.f / (1.f + expf(-go));
                    float cn = sf * cold[b] + si * tanhf(gg);
                    cn2[b] = cn;
                    hn2[b] = so * tanhf(cn);
                }
                *(float2*)cp_ = make_float2(cn2[0], cn2[1]);
                float2 hv = make_float2(hn2[0], hn2[1]);
                *(float2*)(hout + (size_t)j * B + bgrp * 2) = hv;
                if (layer == 0)
                    *(float2*)(g_h1seqT + ((size_t)t * H + j) * B + bgrp * 2) = hv;
            }
        }
    }

    // ---------------- FC epilogue: out[b] = h2_last . fcW + fcb ----------------
    grid_barrier(base + ++phase);
    const float* hfin = g_hT1[0];   // last write t=T-1 -> buffer (T & 1) == 0
    int b0 = blockIdx.x * 2;
    float s0 = 0.f, s1 = 0.f;
    for (int j = tid; j < H; j += NTHR) {
        float w = fcW[j];
        s0 += w * hfin[(size_t)j * B + b0];
        s1 += w * hfin[(size_t)j * B + b0 + 1];
    }
    float* red = Abuf;
    red[tid] = s0; red[NTHR + tid] = s1;
    __syncthreads();
    for (int off = NTHR / 2; off > 0; off >>= 1) {
        if (tid < off) {
            red[tid] += red[tid + off];
            red[NTHR + tid] += red[NTHR + tid + off];
        }
        __syncthreads();
    }
    if (tid == 0) {
        out[b0]     = red[0]    + fcb[0];
        out[b0 + 1] = red[NTHR] + fcb[0];
    }
}

// ---------------- launch ----------------
extern "C" void kernel_launch(void* const* d_in, const int* in_sizes, int n_in,
                              void* d_out, int out_size)
{
    const float* x     = (const float*)d_in[0];
    const float* W_ih0 = (const float*)d_in[1];
    const float* W_hh0 = (const float*)d_in[2];
    const float* b_ih0 = (const float*)d_in[3];
    const float* b_hh0 = (const float*)d_in[4];
    const float* W_ih1 = (const float*)d_in[5];
    const float* W_hh1 = (const float*)d_in[6];
    const float* b_ih1 = (const float*)d_in[7];
    const float* b_hh1 = (const float*)d_in[8];
    const float* fc_W  = (const float*)d_in[9];
    const float* fc_b  = (const float*)d_in[10];
    float* out = (float*)d_out;

    cudaFuncSetAttribute(lstm_persist,
                         cudaFuncAttributeMaxDynamicSharedMemorySize, 131072);

    lstm_persist<<<NCTA, NTHR, 131072>>>(x,
                                         W_ih0, W_hh0, b_ih0, b_hh0,
                                         W_ih1, W_hh1, b_ih1, b_hh1,
                                         fc_W, fc_b, out);
}

// round 12
// speedup vs baseline: 1.4989x; 1.1800x over previous
#include <cuda_runtime.h>
#include <math.h>

#define H 512
#define B 256
#define T 512
#define DIN 64
#define KC 32           // k-chunk size (rows of 256 batch floats)
#define NCTA 128
#define NTHR 128
#define HB (H * B)

// ---------------- persistent device state (allocation-free) ----------------
__device__ float g_xT[(size_t)T * DIN * B];          // x transposed: [t][d][b] (32 MB)
__device__ float g_h1seqT[(size_t)T * H * B];        // layer-0 output: [t][j][b] (256 MB)
__device__ float g_hT0[2][HB];                       // layer-0 hidden, [j][b], double-buffered
__device__ float g_hT1[2][HB];                       // layer-1 hidden
__device__ float g_cT0[HB];                          // cells, [j][b]
__device__ float g_cT1[HB];
__device__ unsigned g_bar_cnt;
__device__ volatile unsigned g_bar_phase;

// ---------------- helpers ----------------
#define FMAX2(d, a, b) asm("fma.rn.f32x2 %0, %1, %2, %0;" : "+l"(d) : "l"(a), "l"(b))

__device__ __forceinline__ unsigned long long splat2(float v) {
    unsigned long long r;
    unsigned u = __float_as_uint(v);
    asm("mov.b64 %0, {%1, %1};" : "=l"(r) : "r"(u));
    return r;
}

__device__ __forceinline__ void cp_async16(void* s, const void* g) {
    unsigned sa = (unsigned)__cvta_generic_to_shared(s);
    asm volatile("cp.async.cg.shared.global [%0], [%1], 16;" :: "r"(sa), "l"(g));
}
#define CP_COMMIT() asm volatile("cp.async.commit_group;")
#define CP_WAIT0()  asm volatile("cp.async.wait_group 0;")
#define CP_WAIT1()  asm volatile("cp.async.wait_group 1;")

__device__ __forceinline__ float2 unpack2(unsigned long long v) {
    float2 r;
    r.x = __uint_as_float((unsigned)v);
    r.y = __uint_as_float((unsigned)(v >> 32));
    return r;
}

__device__ __forceinline__ void grid_barrier(unsigned target) {
    __threadfence();
    __syncthreads();
    if (threadIdx.x == 0) {
        unsigned a = atomicAdd(&g_bar_cnt, 1);
        if (a == gridDim.x - 1) {
            g_bar_cnt = 0;
            __threadfence();
            g_bar_phase = target;           // release
        } else {
            while (g_bar_phase < target) {} // spin
        }
        __threadfence();
    }
    __syncthreads();
}

// Fused cell update for one layer segment (gate order i,f,g,o).
__device__ __forceinline__ void cell_update(
    const unsigned long long (&acc)[2][2][4], const float (&bias)[2][4],
    float* __restrict__ cbuf, float* __restrict__ hout, float* __restrict__ seq,
    int ju0, int bgrp)
{
    #pragma unroll
    for (int u = 0; u < 2; u++) {
        int j = ju0 + u;
        float* cp_ = cbuf + (size_t)j * B + bgrp * 4;
        float4 cv = *(const float4*)cp_;
        float cold[4] = {cv.x, cv.y, cv.z, cv.w};
        float cn4[4], hn4[4];
        #pragma unroll
        for (int b = 0; b < 4; b++) {
            float2 pif = unpack2(acc[u][0][b]);
            float2 pgo = unpack2(acc[u][1][b]);
            float gi = pif.x + bias[u][0];
            float gf = pif.y + bias[u][1];
            float gg = pgo.x + bias[u][2];
            float go = pgo.y + bias[u][3];
            float si = 1.f / (1.f + expf(-gi));
            float sf = 1.f / (1.f + expf(-gf));
            float so = 1.f / (1.f + expf(-go));
            float cn = sf * cold[b] + si * tanhf(gg);
            cn4[b] = cn;
            hn4[b] = so * tanhf(cn);
        }
        *(float4*)cp_ = make_float4(cn4[0], cn4[1], cn4[2], cn4[3]);
        float4 hv = make_float4(hn4[0], hn4[1], hn4[2], hn4[3]);
        *(float4*)(hout + (size_t)j * B + bgrp * 4) = hv;
        if (seq)
            *(float4*)(seq + (size_t)j * B + bgrp * 4) = hv;
    }
}

// ---------------- single persistent kernel ----------------
// 128 CTAs x 128 threads. CTA bx owns hidden units [4*bx, 4*bx+4), all 256 batch,
// all 4 gates. Thread tile: 4 batches x 2 units x 4 gates, f32x2 over gate pairs
// (i,f)/(g,o). Layer-merged epochs: epoch e = layer0@t=e + layer1@t=e-1, ONE
// grid barrier per epoch. Triple-buffered A chunks, one __syncthreads per chunk.
__global__ __launch_bounds__(NTHR, 1) void lstm_persist(
    const float* __restrict__ x,
    const float* __restrict__ W_ih0, const float* __restrict__ W_hh0,
    const float* __restrict__ b_ih0, const float* __restrict__ b_hh0,
    const float* __restrict__ W_ih1, const float* __restrict__ W_hh1,
    const float* __restrict__ b_ih1, const float* __restrict__ b_hh1,
    const float* __restrict__ fcW,  const float* __restrict__ fcb,
    float* __restrict__ out)
{
    extern __shared__ char smem[];
    float* Abuf = (float*)smem;                       // 3 x 8192 floats = 96 KB
    float* Wsh0 = (float*)(smem + 98304);             // 576*16 floats  = 36 KB
    float* Wsh1 = (float*)(smem + 98304 + 36864);     // 1024*16 floats = 64 KB

    const int tid  = threadIdx.x;
    const int bgrp = tid & 63;        // batch group (0..63), 4 batches each
    const int ggrp = tid >> 6;        // unit pair (0..1)
    const int jblk = blockIdx.x * 4;  // CTA's first hidden unit
    const int ju0  = jblk + ggrp * 2; // thread's first unit

    const unsigned base = g_bar_phase;
    unsigned phase = 0;

    // ---- init hidden/cell state ----
    for (int i = blockIdx.x * NTHR + tid; i < HB; i += NCTA * NTHR) {
        g_hT0[0][i] = 0.f; g_cT0[i] = 0.f;
        g_hT1[0][i] = 0.f; g_cT1[i] = 0.f;
    }

    // ---- transpose x: [b][t][d] -> xT[t][d][b] ----
    {
        float* tile = Abuf;  // 32*65 floats
        for (int ti = blockIdx.x; ti < T * (B / 32); ti += NCTA) {
            int t = ti >> 3;
            int bblk = (ti & 7) * 32;
            for (int i = tid; i < 32 * 64; i += NTHR) {
                int b = i >> 6, d = i & 63;
                tile[b * 65 + d] = x[((size_t)(bblk + b) * T + t) * DIN + d];
            }
            __syncthreads();
            for (int i = tid; i < 32 * 64; i += NTHR) {
                int d = i >> 5, b = i & 31;
                g_xT[((size_t)t * DIN + d) * B + bblk + b] = tile[b * 65 + d];
            }
            __syncthreads();
        }
    }

    // ---- load both layers' W slices into SMEM: Wsh[k][unit(4)][gate(4)] ----
    for (int idx = tid; idx < (DIN + H) * 16; idx += NTHR) {
        int k = idx >> 4, u = (idx >> 2) & 3, g = idx & 3;
        int row = g * H + jblk + u;
        Wsh0[idx] = (k < DIN) ? W_ih0[(size_t)row * DIN + k]
                              : W_hh0[(size_t)row * H + (k - DIN)];
    }
    for (int idx = tid; idx < (H + H) * 16; idx += NTHR) {
        int k = idx >> 4, u = (idx >> 2) & 3, g = idx & 3;
        int row = g * H + jblk + u;
        Wsh1[idx] = (k < H) ? W_ih1[(size_t)row * H + k]
                            : W_hh1[(size_t)row * H + (k - H)];
    }
    float b0r[2][4], b1r[2][4];
    #pragma unroll
    for (int u = 0; u < 2; u++)
        #pragma unroll
        for (int g = 0; g < 4; g++) {
            int j = ju0 + u;
            b0r[u][g] = b_ih0[g * H + j] + b_hh0[g * H + j];
            b1r[u][g] = b_ih1[g * H + j] + b_hh1[g * H + j];
        }

    grid_barrier(base + ++phase);

    // ---- epoch loop: e in [0, T]; layer0@t=e (e<T), layer1@t=e-1 (e>0) ----
    for (int e = 0; e <= T; e++) {
        const bool L0a = (e < T), L1a = (e > 0);
        const int t0 = e, t1 = e - 1;
        const float* h0in  = g_hT0[t0 & 1];
        float*       h0out = g_hT0[(t0 + 1) & 1];
        const float* h2in  = g_hT1[t1 & 1];
        float*       h2out = g_hT1[(t1 + 1) & 1];
        const int nch0 = L0a ? 18 : 0;                 // layer-0: 2 x-chunks + 16 h-chunks
        const int nch  = nch0 + (L1a ? 32 : 0);        // layer-1: 16 seq + 16 h

        // chunk source resolver
        auto srcp = [&](int ci) -> const float* {
            if (ci < nch0)
                return (ci < 2) ? (g_xT + (size_t)t0 * DIN * B + (size_t)ci * KC * B)
                                : (h0in + (size_t)(ci - 2) * KC * B);
            int cj = ci - nch0;
            return (cj < 16) ? (g_h1seqT + (size_t)t1 * H * B + (size_t)cj * KC * B)
                             : (h2in + (size_t)(cj - 16) * KC * B);
        };
        auto issue = [&](int ci) {
            const float* s = srcp(ci);
            float* dst = Abuf + (ci % 3) * (KC * B);
            #pragma unroll
            for (int i = 0; i < 16; i++) {
                int idx = tid + i * NTHR;   // float4 index < 2048
                cp_async16(dst + idx * 4, s + idx * 4);
            }
            CP_COMMIT();
        };

        issue(0);
        if (1 < nch) issue(1);

        unsigned long long acc[2][2][4];   // [unit][(i,f)/(g,o)][batch]
        #pragma unroll
        for (int u = 0; u < 2; u++)
            #pragma unroll
            for (int p = 0; p < 2; p++)
                #pragma unroll
                for (int b = 0; b < 4; b++) acc[u][p][b] = 0ull;

        for (int ci = 0; ci < nch; ci++) {
            if (ci + 1 < nch) CP_WAIT1(); else CP_WAIT0();
            __syncthreads();                       // all warps done with chunk ci-1
            if (ci + 2 < nch) issue(ci + 2);       // lands in buffer (ci-1)%3: safe

            const float* A  = Abuf + (ci % 3) * (KC * B) + bgrp * 4;
            const float* Wk = ((ci < nch0) ? (Wsh0 + (size_t)ci * KC * 16)
                                           : (Wsh1 + (size_t)(ci - nch0) * KC * 16))
                              + ggrp * 8;
            #pragma unroll 8
            for (int kk = 0; kk < KC; kk++) {
                float4 av = *(const float4*)(A + kk * B);
                longlong2 w0 = *(const longlong2*)(Wk + kk * 16);      // unit0 (i,f),(g,o)
                longlong2 w1 = *(const longlong2*)(Wk + kk * 16 + 4);  // unit1
                unsigned long long aa0 = splat2(av.x);
                unsigned long long aa1 = splat2(av.y);
                unsigned long long aa2 = splat2(av.z);
                unsigned long long aa3 = splat2(av.w);
                FMAX2(acc[0][0][0], aa0, (unsigned long long)w0.x);
                FMAX2(acc[0][0][1], aa1, (unsigned long long)w0.x);
                FMAX2(acc[0][0][2], aa2, (unsigned long long)w0.x);
                FMAX2(acc[0][0][3], aa3, (unsigned long long)w0.x);
                FMAX2(acc[0][1][0], aa0, (unsigned long long)w0.y);
                FMAX2(acc[0][1][1], aa1, (unsigned long long)w0.y);
                FMAX2(acc[0][1][2], aa2, (unsigned long long)w0.y);
                FMAX2(acc[0][1][3], aa3, (unsigned long long)w0.y);
                FMAX2(acc[1][0][0], aa0, (unsigned long long)w1.x);
                FMAX2(acc[1][0][1], aa1, (unsigned long long)w1.x);
                FMAX2(acc[1][0][2], aa2, (unsigned long long)w1.x);
                FMAX2(acc[1][0][3], aa3, (unsigned long long)w1.x);
                FMAX2(acc[1][1][0], aa0, (unsigned long long)w1.y);
                FMAX2(acc[1][1][1], aa1, (unsigned long long)w1.y);
                FMAX2(acc[1][1][2], aa2, (unsigned long long)w1.y);
                FMAX2(acc[1][1][3], aa3, (unsigned long long)w1.y);
            }

            if (ci == nch0 - 1) {   // layer-0 epilogue (only reached when L0a)
                cell_update(acc, b0r, g_cT0, h0out,
                            g_h1seqT + (size_t)t0 * H * B, ju0, bgrp);
                #pragma unroll
                for (int u = 0; u < 2; u++)
                    #pragma unroll
                    for (int p = 0; p < 2; p++)
                        #pragma unroll
                        for (int b = 0; b < 4; b++) acc[u][p][b] = 0ull;
            }
        }
        if (L1a)
            cell_update(acc, b1r, g_cT1, h2out, nullptr, ju0, bgrp);

        grid_barrier(base + ++phase);
    }

    // ---------------- FC epilogue: out[b] = h2_last . fcW + fcb ----------------
    const float* hfin = g_hT1[0];   // last layer-1 write (t1=511) -> buffer 0
    int b0 = blockIdx.x * 2;
    float s0 = 0.f, s1 = 0.f;
    for (int j = tid; j < H; j += NTHR) {
        float w = fcW[j];
        s0 += w * hfin[(size_t)j * B + b0];
        s1 += w * hfin[(size_t)j * B + b0 + 1];
    }
    float* red = Abuf;
    red[tid] = s0; red[NTHR + tid] = s1;
    __syncthreads();
    for (int off = NTHR / 2; off > 0; off >>= 1) {
        if (tid < off) {
            red[tid] += red[tid + off];
            red[NTHR + tid] += red[NTHR + tid + off];
        }
        __syncthreads();
    }
    if (tid == 0) {
        out[b0]     = red[0]    + fcb[0];
        out[b0 + 1] = red[NTHR] + fcb[0];
    }
}

// ---------------- launch ----------------
extern "C" void kernel_launch(void* const* d_in, const int* in_sizes, int n_in,
                              void* d_out, int out_size)
{
    const float* x     = (const float*)d_in[0];
    const float* W_ih0 = (const float*)d_in[1];
    const float* W_hh0 = (const float*)d_in[2];
    const float* b_ih0 = (const float*)d_in[3];
    const float* b_hh0 = (const float*)d_in[4];
    const float* W_ih1 = (const float*)d_in[5];
    const float* W_hh1 = (const float*)d_in[6];
    const float* b_ih1 = (const float*)d_in[7];
    const float* b_hh1 = (const float*)d_in[8];
    const float* fc_W  = (const float*)d_in[9];
    const float* fc_b  = (const float*)d_in[10];
    float* out = (float*)d_out;

    const int smem_bytes = 98304 + 36864 + 65536;   // 200704
    cudaFuncSetAttribute(lstm_persist,
                         cudaFuncAttributeMaxDynamicSharedMemorySize, smem_bytes);

    lstm_persist<<<NCTA, NTHR, smem_bytes>>>(x,
                                             W_ih0, W_hh0, b_ih0, b_hh0,
                                             W_ih1, W_hh1, b_ih1, b_hh1,
                                             fc_W, fc_b, out);
}